// round 5
// baseline (speedup 1.0000x reference)
#include <cuda_runtime.h>

#define M_DIM 8192
#define N_DIM 1024
#define IN_DIM 1024
#define KV (IN_DIM * 4)   // virtual K = 4096

// Scratch (allocation-free rule: __device__ globals)
__device__ float g_F[(size_t)M_DIM * KV];      // 128 MB feature matrix [M][KV]
__device__ float g_Wp[(size_t)KV * N_DIM];     // 16 MB packed weights  [KV][N]
__device__ float g_biasp[N_DIM];               // bias + sum_i C[o,i,0]

// ---------------------------------------------------------------------------
// Feature map: F[b][i*4 + {0,1,2,3}] = x, x^2, x^3, silu(x)
// ---------------------------------------------------------------------------
__global__ void feat_kernel(const float* __restrict__ x) {
    int idx = blockIdx.x * blockDim.x + threadIdx.x;   // over M*IN = 8M
    if (idx >= M_DIM * IN_DIM) return;
    float v  = x[idx];
    float v2 = v * v;
    float v3 = v2 * v;
    float s  = v / (1.0f + expf(-v));
    reinterpret_cast<float4*>(g_F)[idx] = make_float4(v, v2, v3, s);
}

// ---------------------------------------------------------------------------
// Weight pack: Wp[(i*4+f)*N + o] = { C[o,i,1], C[o,i,2], C[o,i,3], W[o,i] }
// o varies fastest across threads -> coalesced writes.
// ---------------------------------------------------------------------------
__global__ void pack_kernel(const float* __restrict__ tc,
                            const float* __restrict__ bw) {
    int idx = blockIdx.x * blockDim.x + threadIdx.x;   // over OUT*IN = 1M
    if (idx >= N_DIM * IN_DIM) return;
    int o = idx & (N_DIM - 1);
    int i = idx >> 10;
    float4 c = reinterpret_cast<const float4*>(tc)[(size_t)o * IN_DIM + i];
    float  w = bw[(size_t)o * IN_DIM + i];
    size_t base = (size_t)(i * 4) * N_DIM + o;
    g_Wp[base + 0 * N_DIM] = c.y;   // coeff of x^1
    g_Wp[base + 1 * N_DIM] = c.z;   // coeff of x^2
    g_Wp[base + 2 * N_DIM] = c.w;   // coeff of x^3
    g_Wp[base + 3 * N_DIM] = w;     // base weight (pairs with silu)
}

// ---------------------------------------------------------------------------
// bias'[o] = bias[o] + sum_i C[o,i,0]   (the x^0 Taylor term)
// ---------------------------------------------------------------------------
__global__ void bias_kernel(const float* __restrict__ tc,
                            const float* __restrict__ bias) {
    int o = blockIdx.x;
    float s = 0.f;
    for (int i = threadIdx.x; i < IN_DIM; i += 256)
        s += tc[(size_t)o * (IN_DIM * 4) + (size_t)i * 4];
    #pragma unroll
    for (int off = 16; off; off >>= 1)
        s += __shfl_down_sync(0xffffffffu, s, off);
    __shared__ float red[8];
    if ((threadIdx.x & 31) == 0) red[threadIdx.x >> 5] = s;
    __syncthreads();
    if (threadIdx.x < 8) {
        s = red[threadIdx.x];
        #pragma unroll
        for (int off = 4; off; off >>= 1)
            s += __shfl_down_sync(0xffu, s, off);
        if (threadIdx.x == 0) g_biasp[o] = s + bias[o];
    }
}

// ---------------------------------------------------------------------------
// SGEMM: out[M,N] = F[M,KV] * Wp[KV,N] + bias'
// BM=128, BN=128, BK=16, 256 threads, 8x8 per-thread tile.
// ---------------------------------------------------------------------------
__global__ void __launch_bounds__(256, 2) gemm_kernel(float* __restrict__ out) {
    __shared__ float As[16][132];   // +4 pad: rows stay 16B-aligned (528B)
    __shared__ float Bs[16][128];

    const int tid = threadIdx.x;
    const int bm  = blockIdx.y * 128;
    const int bn  = blockIdx.x * 128;

    // A-tile load mapping: 2 x float4 per thread
    const int arow = tid >> 2;          // 0..63
    const int acol = (tid & 3) << 2;    // 0,4,8,12
    // B-tile load mapping: 2 x float4 per thread
    const int brow = tid >> 5;          // 0..7
    const int bcol = (tid & 31) << 2;   // 0..124

    // compute mapping: 16x16 thread grid, 8x8 micro-tile
    const int tx = (tid & 15) << 3;     // output col offset
    const int ty = (tid >> 4) << 3;     // output row offset

    float acc[8][8] = {};

    const float* Abase = g_F + (size_t)bm * KV;

    for (int k0 = 0; k0 < KV; k0 += 16) {
        float4 a0 = *reinterpret_cast<const float4*>(
            Abase + (size_t)arow * KV + k0 + acol);
        float4 a1 = *reinterpret_cast<const float4*>(
            Abase + (size_t)(arow + 64) * KV + k0 + acol);
        float4 b0 = *reinterpret_cast<const float4*>(
            g_Wp + (size_t)(k0 + brow) * N_DIM + bn + bcol);
        float4 b1 = *reinterpret_cast<const float4*>(
            g_Wp + (size_t)(k0 + brow + 8) * N_DIM + bn + bcol);

        As[acol + 0][arow] = a0.x;
        As[acol + 1][arow] = a0.y;
        As[acol + 2][arow] = a0.z;
        As[acol + 3][arow] = a0.w;
        As[acol + 0][arow + 64] = a1.x;
        As[acol + 1][arow + 64] = a1.y;
        As[acol + 2][arow + 64] = a1.z;
        As[acol + 3][arow + 64] = a1.w;
        *reinterpret_cast<float4*>(&Bs[brow][bcol])     = b0;
        *reinterpret_cast<float4*>(&Bs[brow + 8][bcol]) = b1;

        __syncthreads();

        #pragma unroll
        for (int kk = 0; kk < 16; kk++) {
            float ra[8], rb[8];
            *reinterpret_cast<float4*>(&ra[0]) =
                *reinterpret_cast<const float4*>(&As[kk][ty]);
            *reinterpret_cast<float4*>(&ra[4]) =
                *reinterpret_cast<const float4*>(&As[kk][ty + 4]);
            *reinterpret_cast<float4*>(&rb[0]) =
                *reinterpret_cast<const float4*>(&Bs[kk][tx]);
            *reinterpret_cast<float4*>(&rb[4]) =
                *reinterpret_cast<const float4*>(&Bs[kk][tx + 4]);
            #pragma unroll
            for (int i = 0; i < 8; i++)
                #pragma unroll
                for (int j = 0; j < 8; j++)
                    acc[i][j] = fmaf(ra[i], rb[j], acc[i][j]);
        }
        __syncthreads();
    }

    // epilogue: add folded bias, store
    #pragma unroll
    for (int i = 0; i < 8; i++) {
        const size_t row = (size_t)(bm + ty + i) * N_DIM + bn + tx;
        #pragma unroll
        for (int j = 0; j < 8; j += 4) {
            float4 v;
            v.x = acc[i][j + 0] + g_biasp[bn + tx + j + 0];
            v.y = acc[i][j + 1] + g_biasp[bn + tx + j + 1];
            v.z = acc[i][j + 2] + g_biasp[bn + tx + j + 2];
            v.w = acc[i][j + 3] + g_biasp[bn + tx + j + 3];
            *reinterpret_cast<float4*>(out + row + j) = v;
        }
    }
}

// ---------------------------------------------------------------------------
extern "C" void kernel_launch(void* const* d_in, const int* in_sizes, int n_in,
                              void* d_out, int out_size) {
    // Identify inputs by element count (all distinct):
    // x: 8192*1024=8388608, base_weight: 1048576, taylor_coeffs: 4194304, bias: 1024
    const float* x = nullptr;
    const float* bw = nullptr;
    const float* tc = nullptr;
    const float* bias = nullptr;
    for (int i = 0; i < n_in; i++) {
        long sz = in_sizes[i];
        if      (sz == 8388608L) x    = (const float*)d_in[i];
        else if (sz == 1048576L) bw   = (const float*)d_in[i];
        else if (sz == 4194304L) tc   = (const float*)d_in[i];
        else if (sz == 1024L)    bias = (const float*)d_in[i];
    }
    float* out = (float*)d_out;

    feat_kernel<<<(M_DIM * IN_DIM) / 256, 256>>>(x);
    pack_kernel<<<(N_DIM * IN_DIM) / 256, 256>>>(tc, bw);
    bias_kernel<<<N_DIM, 256>>>(tc, bias);

    dim3 grid(N_DIM / 128, M_DIM / 128);
    gemm_kernel<<<grid, 256>>>(out);
}

// round 6
// speedup vs baseline: 1.0029x; 1.0029x over previous
#include <cuda_runtime.h>

#define M_DIM 8192
#define N_DIM 1024
#define IN_DIM 1024
#define KV (IN_DIM * 4)   // virtual K = 4096

// Scratch (allocation-free rule: __device__ globals)
__device__ float g_F[(size_t)M_DIM * KV];      // 128 MB feature matrix [M][KV]
__device__ float g_Wp[(size_t)KV * N_DIM];     // 16 MB packed weights  [KV][N]
__device__ float g_biasp[N_DIM];               // bias + sum_i C[o,i,0]

// ---------------------------------------------------------------------------
// Feature map: F[b][i*4 + {0,1,2,3}] = x, x^2, x^3, silu(x)
// ---------------------------------------------------------------------------
__global__ void feat_kernel(const float* __restrict__ x) {
    int idx = blockIdx.x * blockDim.x + threadIdx.x;   // over M*IN = 8M
    if (idx >= M_DIM * IN_DIM) return;
    float v  = x[idx];
    float v2 = v * v;
    float v3 = v2 * v;
    float s  = v / (1.0f + expf(-v));
    reinterpret_cast<float4*>(g_F)[idx] = make_float4(v, v2, v3, s);
}

// ---------------------------------------------------------------------------
// Weight pack: Wp[(i*4+f)*N + o] = { C[o,i,1], C[o,i,2], C[o,i,3], W[o,i] }
// o varies fastest across threads -> coalesced writes.
// ---------------------------------------------------------------------------
__global__ void pack_kernel(const float* __restrict__ tc,
                            const float* __restrict__ bw) {
    int idx = blockIdx.x * blockDim.x + threadIdx.x;   // over OUT*IN = 1M
    if (idx >= N_DIM * IN_DIM) return;
    int o = idx & (N_DIM - 1);
    int i = idx >> 10;
    float4 c = reinterpret_cast<const float4*>(tc)[(size_t)o * IN_DIM + i];
    float  w = bw[(size_t)o * IN_DIM + i];
    size_t base = (size_t)(i * 4) * N_DIM + o;
    g_Wp[base + 0 * N_DIM] = c.y;   // coeff of x^1
    g_Wp[base + 1 * N_DIM] = c.z;   // coeff of x^2
    g_Wp[base + 2 * N_DIM] = c.w;   // coeff of x^3
    g_Wp[base + 3 * N_DIM] = w;     // base weight (pairs with silu)
}

// ---------------------------------------------------------------------------
// bias'[o] = bias[o] + sum_i C[o,i,0]   (the x^0 Taylor term)
// ---------------------------------------------------------------------------
__global__ void bias_kernel(const float* __restrict__ tc,
                            const float* __restrict__ bias) {
    int o = blockIdx.x;
    float s = 0.f;
    for (int i = threadIdx.x; i < IN_DIM; i += 256)
        s += tc[(size_t)o * (IN_DIM * 4) + (size_t)i * 4];
    #pragma unroll
    for (int off = 16; off; off >>= 1)
        s += __shfl_down_sync(0xffffffffu, s, off);
    __shared__ float red[8];
    if ((threadIdx.x & 31) == 0) red[threadIdx.x >> 5] = s;
    __syncthreads();
    if (threadIdx.x < 8) {
        s = red[threadIdx.x];
        #pragma unroll
        for (int off = 4; off; off >>= 1)
            s += __shfl_down_sync(0xffu, s, off);
        if (threadIdx.x == 0) g_biasp[o] = s + bias[o];
    }
}

// ---------------------------------------------------------------------------
// SGEMM: out[M,N] = F[M,KV] * Wp[KV,N] + bias'
// BM=128, BN=128, BK=16, 256 threads, 8x8 per-thread tile.
// ---------------------------------------------------------------------------
__global__ void __launch_bounds__(256, 2) gemm_kernel(float* __restrict__ out) {
    __shared__ float As[16][132];   // +4 pad: rows stay 16B-aligned (528B)
    __shared__ float Bs[16][128];

    const int tid = threadIdx.x;
    const int bm  = blockIdx.y * 128;
    const int bn  = blockIdx.x * 128;

    // A-tile load mapping: 2 x float4 per thread
    const int arow = tid >> 2;          // 0..63
    const int acol = (tid & 3) << 2;    // 0,4,8,12
    // B-tile load mapping: 2 x float4 per thread
    const int brow = tid >> 5;          // 0..7
    const int bcol = (tid & 31) << 2;   // 0..124

    // compute mapping: 16x16 thread grid, 8x8 micro-tile
    const int tx = (tid & 15) << 3;     // output col offset
    const int ty = (tid >> 4) << 3;     // output row offset

    float acc[8][8] = {};

    const float* Abase = g_F + (size_t)bm * KV;

    for (int k0 = 0; k0 < KV; k0 += 16) {
        float4 a0 = *reinterpret_cast<const float4*>(
            Abase + (size_t)arow * KV + k0 + acol);
        float4 a1 = *reinterpret_cast<const float4*>(
            Abase + (size_t)(arow + 64) * KV + k0 + acol);
        float4 b0 = *reinterpret_cast<const float4*>(
            g_Wp + (size_t)(k0 + brow) * N_DIM + bn + bcol);
        float4 b1 = *reinterpret_cast<const float4*>(
            g_Wp + (size_t)(k0 + brow + 8) * N_DIM + bn + bcol);

        As[acol + 0][arow] = a0.x;
        As[acol + 1][arow] = a0.y;
        As[acol + 2][arow] = a0.z;
        As[acol + 3][arow] = a0.w;
        As[acol + 0][arow + 64] = a1.x;
        As[acol + 1][arow + 64] = a1.y;
        As[acol + 2][arow + 64] = a1.z;
        As[acol + 3][arow + 64] = a1.w;
        *reinterpret_cast<float4*>(&Bs[brow][bcol])     = b0;
        *reinterpret_cast<float4*>(&Bs[brow + 8][bcol]) = b1;

        __syncthreads();

        #pragma unroll
        for (int kk = 0; kk < 16; kk++) {
            float ra[8], rb[8];
            *reinterpret_cast<float4*>(&ra[0]) =
                *reinterpret_cast<const float4*>(&As[kk][ty]);
            *reinterpret_cast<float4*>(&ra[4]) =
                *reinterpret_cast<const float4*>(&As[kk][ty + 4]);
            *reinterpret_cast<float4*>(&rb[0]) =
                *reinterpret_cast<const float4*>(&Bs[kk][tx]);
            *reinterpret_cast<float4*>(&rb[4]) =
                *reinterpret_cast<const float4*>(&Bs[kk][tx + 4]);
            #pragma unroll
            for (int i = 0; i < 8; i++)
                #pragma unroll
                for (int j = 0; j < 8; j++)
                    acc[i][j] = fmaf(ra[i], rb[j], acc[i][j]);
        }
        __syncthreads();
    }

    // epilogue: add folded bias, store
    #pragma unroll
    for (int i = 0; i < 8; i++) {
        const size_t row = (size_t)(bm + ty + i) * N_DIM + bn + tx;
        #pragma unroll
        for (int j = 0; j < 8; j += 4) {
            float4 v;
            v.x = acc[i][j + 0] + g_biasp[bn + tx + j + 0];
            v.y = acc[i][j + 1] + g_biasp[bn + tx + j + 1];
            v.z = acc[i][j + 2] + g_biasp[bn + tx + j + 2];
            v.w = acc[i][j + 3] + g_biasp[bn + tx + j + 3];
            *reinterpret_cast<float4*>(out + row + j) = v;
        }
    }
}

// ---------------------------------------------------------------------------
extern "C" void kernel_launch(void* const* d_in, const int* in_sizes, int n_in,
                              void* d_out, int out_size) {
    // Identify inputs by element count (all distinct):
    // x: 8192*1024=8388608, base_weight: 1048576, taylor_coeffs: 4194304, bias: 1024
    const float* x = nullptr;
    const float* bw = nullptr;
    const float* tc = nullptr;
    const float* bias = nullptr;
    for (int i = 0; i < n_in; i++) {
        long sz = in_sizes[i];
        if      (sz == 8388608L) x    = (const float*)d_in[i];
        else if (sz == 1048576L) bw   = (const float*)d_in[i];
        else if (sz == 4194304L) tc   = (const float*)d_in[i];
        else if (sz == 1024L)    bias = (const float*)d_in[i];
    }
    float* out = (float*)d_out;

    feat_kernel<<<(M_DIM * IN_DIM) / 256, 256>>>(x);
    pack_kernel<<<(N_DIM * IN_DIM) / 256, 256>>>(tc, bw);
    bias_kernel<<<N_DIM, 256>>>(tc, bias);

    dim3 grid(N_DIM / 128, M_DIM / 128);
    gemm_kernel<<<grid, 256>>>(out);
}